// round 5
// baseline (speedup 1.0000x reference)
#include <cuda_runtime.h>
#include <mma.h>
#include <cstdint>
#include <cstddef>

using namespace nvcuda;

#define BB 4
#define PP 256
#define FIN 512
#define FOUT 512
#define NROWS (BB*PP)   // 1024

// ---------------- device scratch (no allocations allowed) -------------------
__device__ float g_H[NROWS * FOUT];          // fc output h (+bias), 2 MB
__device__ float g_inv[NROWS];               // 1/max(||h||, 1e-12)
__device__ unsigned long long g_h1[NROWS];
__device__ unsigned long long g_h2[NROWS];
__device__ double g_loss;

__device__ __forceinline__ unsigned long long mix64(unsigned long long x) {
    x ^= x >> 30; x *= 0xbf58476d1ce4e5b9ULL;
    x ^= x >> 27; x *= 0x94d049bb133111ebULL;
    x ^= x >> 31;
    return x;
}

// ================= GEMM1 (+ label-hash prologue) ============================
// g_H = inputs(1024x512) @ W^T + bias. grid (8 n, 16 m) = 128 CTAs x 256 thr.
// 8 warps: warp grid 4 rows x 2 cols, warp tile 16x32 (1 a-frag, 2 b-frags).
__global__ __launch_bounds__(256, 1)
void gemm1_tc(const float* __restrict__ A, const float* __restrict__ W,
              const float* __restrict__ bias, const float* __restrict__ labels) {
    __shared__ float As[2][64][36];
    __shared__ float Bs[2][64][36];

    const int tid = threadIdx.x;
    const int wid = tid >> 5, lane = tid & 31;

    // ---- hash prologue: 128 CTAs x 8 warps = 1024 warps = 1 label row each
    {
        int gwarp = (blockIdx.y * gridDim.x + blockIdx.x) * 8 + wid;
        const float4* row = reinterpret_cast<const float4*>(labels + (size_t)gwarp * FIN);
        unsigned long long h1 = 0ull, h2 = 0ull;
#pragma unroll
        for (int i = 0; i < 4; i++) {
            float4 v = row[lane + 32 * i];
            int fb = (lane + 32 * i) * 4;
            float vv[4] = {v.x, v.y, v.z, v.w};
#pragma unroll
            for (int j = 0; j < 4; j++) {
                unsigned int bits = __float_as_uint(vv[j]);
                if (vv[j] == 0.0f) bits = 0u;     // canonicalize -0 == +0
                unsigned long long x = (unsigned long long)bits
                    ^ ((unsigned long long)(fb + j + 1) * 0x9E3779B97F4A7C15ULL);
                h1 += mix64(x);
                h2 += mix64(x ^ 0xA5A5A5A5DEADBEEFULL);
            }
        }
#pragma unroll
        for (int o = 16; o > 0; o >>= 1) {
            h1 += __shfl_down_sync(0xffffffffu, h1, o);
            h2 += __shfl_down_sync(0xffffffffu, h2, o);
        }
        if (lane == 0) { g_h1[gwarp] = h1; g_h2[gwarp] = h2; }
    }

    // ---- GEMM
    const int n0 = blockIdx.x * 64;
    const int m0 = blockIdx.y * 64;
    const int wr = wid >> 1;          // 0..3 -> rows wr*16
    const int wc = wid & 1;           // 0..1 -> cols wc*32
    const int r0 = tid >> 3;          // 0..31
    const int kc = tid & 7;

    const float* Arow = A + (size_t)(m0 + r0) * FIN + kc * 4;
    const float* Brow = W + (size_t)(n0 + r0) * FIN + kc * 4;

    float4 pa[2], pb[2];
    auto LDG = [&](int s) {
#pragma unroll
        for (int q = 0; q < 2; q++) {
            pa[q] = *reinterpret_cast<const float4*>(Arow + (size_t)(32 * q) * FIN + s * 32);
            pb[q] = *reinterpret_cast<const float4*>(Brow + (size_t)(32 * q) * FIN + s * 32);
        }
    };
    auto STS = [&](int buf) {
#pragma unroll
        for (int q = 0; q < 2; q++) {
            int r = r0 + 32 * q;
            float4 ca = make_float4(wmma::__float_to_tf32(pa[q].x), wmma::__float_to_tf32(pa[q].y),
                                    wmma::__float_to_tf32(pa[q].z), wmma::__float_to_tf32(pa[q].w));
            float4 cb = make_float4(wmma::__float_to_tf32(pb[q].x), wmma::__float_to_tf32(pb[q].y),
                                    wmma::__float_to_tf32(pb[q].z), wmma::__float_to_tf32(pb[q].w));
            *reinterpret_cast<float4*>(&As[buf][r][kc * 4]) = ca;
            *reinterpret_cast<float4*>(&Bs[buf][r][kc * 4]) = cb;
        }
    };

    wmma::fragment<wmma::accumulator, 16, 16, 8, float> c0, c1;
    wmma::fill_fragment(c0, 0.0f);
    wmma::fill_fragment(c1, 0.0f);

    LDG(0);
    STS(0);
    __syncthreads();

#pragma unroll 1
    for (int s = 0; s < 16; s++) {
        const int buf = s & 1;
        if (s + 1 < 16) LDG(s + 1);
#pragma unroll
        for (int ks = 0; ks < 4; ks++) {
            wmma::fragment<wmma::matrix_a, 16, 16, 8, wmma::precision::tf32, wmma::row_major> a;
            wmma::fragment<wmma::matrix_b, 16, 16, 8, wmma::precision::tf32, wmma::col_major> b0, b1;
            wmma::load_matrix_sync(a,  &As[buf][wr * 16][ks * 8], 36);
            wmma::load_matrix_sync(b0, &Bs[buf][wc * 32][ks * 8], 36);
            wmma::load_matrix_sync(b1, &Bs[buf][wc * 32 + 16][ks * 8], 36);
            wmma::mma_sync(c0, a, b0, c0);
            wmma::mma_sync(c1, a, b1, c1);
        }
        if (s + 1 < 16) STS(buf ^ 1);
        __syncthreads();
    }

    // epilogue: stage + bias + vectorized store
    float* stage = &As[0][0][0];      // 4608 floats >= 64*68 = 4352
    wmma::store_matrix_sync(stage + (size_t)(wr * 16) * 68 + wc * 32,      c0, 68, wmma::mem_row_major);
    wmma::store_matrix_sync(stage + (size_t)(wr * 16) * 68 + wc * 32 + 16, c1, 68, wmma::mem_row_major);
    __syncthreads();
#pragma unroll
    for (int t = 0; t < 4; t++) {
        int f4 = tid + t * 256;
        int row = f4 >> 4, c4 = (f4 & 15) * 4;
        float4 v = *reinterpret_cast<const float4*>(stage + (size_t)row * 68 + c4);
        float4 bv = *reinterpret_cast<const float4*>(bias + n0 + c4);
        v.x += bv.x; v.y += bv.y; v.z += bv.z; v.w += bv.w;
        *reinterpret_cast<float4*>(g_H + (size_t)(m0 + row) * FOUT + n0 + c4) = v;
    }
}

// ================= row norms (fp32, from g_H) ===============================
// 128 blocks x 256 thr = 1024 warps, one H row each. Also zeroes g_loss.
__global__ void norm_kernel() {
    if (blockIdx.x == 0 && threadIdx.x == 0) g_loss = 0.0;
    int gwarp = blockIdx.x * 8 + (threadIdx.x >> 5);
    int lane = threadIdx.x & 31;
    const float4* row = reinterpret_cast<const float4*>(g_H + (size_t)gwarp * FOUT);
    float ss = 0.0f;
#pragma unroll
    for (int i = 0; i < 4; i++) {
        float4 v = row[lane + 32 * i];
        ss += v.x * v.x + v.y * v.y + v.z * v.z + v.w * v.w;
    }
#pragma unroll
    for (int o = 16; o > 0; o >>= 1) ss += __shfl_xor_sync(0xffffffffu, ss, o);
    if (lane == 0) g_inv[gwarp] = 1.0f / fmaxf(sqrtf(ss), 1e-12f);
}

// ================= fused Gram + softmax + KL ================================
// grid (16 row-tiles, 4 batches) = 64 CTAs x 256 thr (8 warps).
// Each CTA: S_tile[16 x 256] = H[m0:m0+16] @ H_b^T via WMMA (K streamed 32-wide,
// double-buffered), then row softmax + KL on the tile. No Gram buffer in HBM.
__global__ __launch_bounds__(256, 1)
void fused_gram_kl() {
    extern __shared__ float dyn[];
    float* Asm = dyn;                 // [2][16][36]  = 1152 floats
    float* Bsm = dyn + 2 * 16 * 36;   // [2][256][36] = 18432 floats
    __shared__ float inv_s[PP];
    __shared__ unsigned long long sh1[PP];
    __shared__ unsigned long long sh2[PP];
    __shared__ double wsum[8];

    const int tile = blockIdx.x;      // 0..15
    const int b = blockIdx.y;         // 0..3
    const int m0 = tile * 16;
    const int tid = threadIdx.x;
    const int wid = tid >> 5, lane = tid & 31;
    const float* Hb = g_H + (size_t)b * PP * FOUT;

    // batch metadata
    {
        int q = tid;                  // 256 threads exactly
        inv_s[q] = g_inv[b * PP + q];
        sh1[q] = g_h1[b * PP + q];
        sh2[q] = g_h2[b * PP + q];
    }

    // ---- Gram tile via WMMA. A chunk: 16x32 (128 f4); B chunk: 256x32 (2048 f4).
    float4 pf[9];
    auto LDG = [&](int c) {
#pragma unroll
        for (int it = 0; it < 9; it++) {
            int idx = tid + it * 256;
            if (idx < 2176) {
                int isA = idx < 128;
                int j = isA ? idx : idx - 128;
                int row = j >> 3, f = j & 7;
                const float* src = isA
                    ? (Hb + (size_t)(m0 + row) * FOUT + c * 32 + f * 4)
                    : (Hb + (size_t)row * FOUT + c * 32 + f * 4);
                pf[it] = *reinterpret_cast<const float4*>(src);
            }
        }
    };
    auto STS = [&](int buf) {
#pragma unroll
        for (int it = 0; it < 9; it++) {
            int idx = tid + it * 256;
            if (idx < 2176) {
                int isA = idx < 128;
                int j = isA ? idx : idx - 128;
                int row = j >> 3, f = j & 7;
                float4 v = pf[it];
                float4 cv = make_float4(wmma::__float_to_tf32(v.x), wmma::__float_to_tf32(v.y),
                                        wmma::__float_to_tf32(v.z), wmma::__float_to_tf32(v.w));
                float* dst = isA ? (Asm + (size_t)buf * 576  + row * 36 + f * 4)
                                 : (Bsm + (size_t)buf * 9216 + row * 36 + f * 4);
                *reinterpret_cast<float4*>(dst) = cv;
            }
        }
    };

    wmma::fragment<wmma::accumulator, 16, 16, 8, float> c0, c1;
    wmma::fill_fragment(c0, 0.0f);
    wmma::fill_fragment(c1, 0.0f);

    LDG(0);
    STS(0);
    __syncthreads();

#pragma unroll 1
    for (int c = 0; c < 16; c++) {
        const int buf = c & 1;
        if (c + 1 < 16) LDG(c + 1);
#pragma unroll
        for (int ks = 0; ks < 4; ks++) {
            wmma::fragment<wmma::matrix_a, 16, 16, 8, wmma::precision::tf32, wmma::row_major> a;
            wmma::fragment<wmma::matrix_b, 16, 16, 8, wmma::precision::tf32, wmma::col_major> b0, b1;
            wmma::load_matrix_sync(a,  Asm + (size_t)buf * 576 + ks * 8, 36);
            wmma::load_matrix_sync(b0, Bsm + (size_t)buf * 9216 + (wid * 32) * 36 + ks * 8, 36);
            wmma::load_matrix_sync(b1, Bsm + (size_t)buf * 9216 + (wid * 32 + 16) * 36 + ks * 8, 36);
            wmma::mma_sync(c0, a, b0, c0);
            wmma::mma_sync(c1, a, b1, c1);
        }
        if (c + 1 < 16) STS(buf ^ 1);
        __syncthreads();
    }

    // ---- stage S tile [16][260] (overlay onto B smem; all mma reads done)
    float* stage = Bsm;
    wmma::store_matrix_sync(stage + wid * 32,      c0, 260, wmma::mem_row_major);
    wmma::store_matrix_sync(stage + wid * 32 + 16, c1, 260, wmma::mem_row_major);
    __syncthreads();

    // ---- softmax + KL: 8 warps x 2 rows
    const float INV_TAU = 1.0f / 0.07f;
    double local = 0.0;
#pragma unroll
    for (int rr = 0; rr < 2; rr++) {
        const int pl = wid * 2 + rr;              // local row 0..15
        const float* Sr = stage + (size_t)pl * 260;
        const float ip = inv_s[m0 + pl] * INV_TAU;
        float s[8];
        float mx = -1e30f;
#pragma unroll
        for (int j = 0; j < 8; j++) {
            int q = lane + 32 * j;
            s[j] = Sr[q] * ip * inv_s[q];
            mx = fmaxf(mx, s[j]);
        }
#pragma unroll
        for (int o = 16; o > 0; o >>= 1) mx = fmaxf(mx, __shfl_xor_sync(0xffffffffu, mx, o));
        float z = 0.0f;
#pragma unroll
        for (int j = 0; j < 8; j++) z += __expf(s[j] - mx);
#pragma unroll
        for (int o = 16; o > 0; o >>= 1) z += __shfl_xor_sync(0xffffffffu, z, o);
        float lse = mx + logf(z);

        unsigned long long h1p = sh1[m0 + pl], h2p = sh2[m0 + pl];
        int cnt = 0;
        bool match[8];
#pragma unroll
        for (int j = 0; j < 8; j++) {
            int q = lane + 32 * j;
            match[j] = (sh1[q] == h1p) && (sh2[q] == h2p);
            cnt += match[j] ? 1 : 0;
        }
#pragma unroll
        for (int o = 16; o > 0; o >>= 1) cnt += __shfl_xor_sync(0xffffffffu, cnt, o);

        float logn = logf((float)cnt);
        float contrib = 0.0f;
#pragma unroll
        for (int j = 0; j < 8; j++) {
            if (match[j]) {
                float lp = s[j] - lse;
                lp = fminf(fmaxf(lp, -11.512925464970229f),      // log(1e-5)
                           -1.0000050000290891e-05f);            // log(1-1e-5)
                contrib += (-logn - lp);
            }
        }
#pragma unroll
        for (int o = 16; o > 0; o >>= 1) contrib += __shfl_xor_sync(0xffffffffu, contrib, o);
        if (lane == 0) local += (double)contrib / (double)cnt;
    }
    if (lane == 0) wsum[wid] = local;
    __syncthreads();
    if (tid == 0) {
        double blk = 0.0;
#pragma unroll
        for (int i = 0; i < 8; i++) blk += wsum[i];
        atomicAdd(&g_loss, blk);
    }
}

__global__ void finalize_kernel(float* __restrict__ out) {
    if (threadIdx.x == 0) out[0] = (float)(g_loss * (1.0 / (double)(BB * PP)));
}

// ================= launch ====================================================
extern "C" void kernel_launch(void* const* d_in, const int* in_sizes, int n_in,
                              void* d_out, int out_size) {
    const float* inputs = (const float*)d_in[0];
    const float* labels = (const float*)d_in[1];
    const float* W      = (const float*)d_in[2];
    const float* bias   = (const float*)d_in[3];
    float* out = (float*)d_out;

    const int FUSED_SMEM = (2 * 16 * 36 + 2 * 256 * 36) * 4;   // 78336 B
    cudaFuncSetAttribute(fused_gram_kl, cudaFuncAttributeMaxDynamicSharedMemorySize, FUSED_SMEM);

    gemm1_tc<<<dim3(FOUT / 64, NROWS / 64), 256>>>(inputs, W, bias, labels);
    norm_kernel<<<128, 256>>>();
    fused_gram_kl<<<dim3(PP / 16, BB), 256, FUSED_SMEM>>>();
    finalize_kernel<<<1, 32>>>(out);
}

// round 6
// speedup vs baseline: 1.0071x; 1.0071x over previous
#include <cuda_runtime.h>
#include <mma.h>
#include <cstdint>
#include <cstddef>

using namespace nvcuda;

#define BB 4
#define PP 256
#define FIN 512
#define FOUT 512
#define NROWS (BB*PP)   // 1024
#define NCTA 128

// ---------------- device scratch (no allocations allowed) -------------------
__device__ float g_H[NROWS * FOUT];          // fc output h (+bias), 2 MB
__device__ float g_inv[NROWS];               // 1/max(||h||, 1e-12)
__device__ unsigned long long g_h1[NROWS];
__device__ unsigned long long g_h2[NROWS];
__device__ double g_loss;
__device__ unsigned int g_cnt = 0;           // barrier arrival count (self-reset)
__device__ unsigned int g_gen = 0;           // barrier generation (monotonic)
__device__ unsigned int g_done = 0;          // phase-3 completion count (self-reset)

// ---------------- software grid barrier (all NCTA CTAs resident) ------------
__device__ __forceinline__ void grid_barrier() {
    __syncthreads();
    if (threadIdx.x == 0) {
        volatile unsigned int* gen = &g_gen;
        unsigned int g = *gen;
        __threadfence();
        if (atomicAdd(&g_cnt, 1u) == NCTA - 1) {
            *(volatile unsigned int*)&g_cnt = 0;   // reset before release
            __threadfence();
            atomicAdd(&g_gen, 1u);
        } else {
            while (*gen == g) { __nanosleep(64); }
        }
        __threadfence();
    }
    __syncthreads();
}

__device__ __forceinline__ unsigned long long mix64(unsigned long long x) {
    x ^= x >> 30; x *= 0xbf58476d1ce4e5b9ULL;
    x ^= x >> 27; x *= 0x94d049bb133111ebULL;
    x ^= x >> 31;
    return x;
}

// ================= single fused kernel ======================================
// dyn smem: phase1 uses [0, 9216) floats (As/Bs double-buffered 64x36);
//           phase3 uses [0, 19584) floats (Asm 2x16x36, Bsm 2x256x36).
__global__ __launch_bounds__(256, 1)
void fused_all(const float* __restrict__ A, const float* __restrict__ labels,
               const float* __restrict__ W, const float* __restrict__ bias,
               float* __restrict__ out) {
    extern __shared__ float dyn[];
    __shared__ float inv_s[PP];
    __shared__ unsigned long long sh1[PP];
    __shared__ unsigned long long sh2[PP];
    __shared__ double wsum[8];

    const int cta = blockIdx.x;
    const int tid = threadIdx.x;
    const int wid = tid >> 5, lane = tid & 31;

    if (cta == 0 && tid == 0) g_loss = 0.0;

    // ======== phase 0: label hashing (128 CTAs x 8 warps = 1024 rows) =======
    {
        int gwarp = cta * 8 + wid;
        const float4* row = reinterpret_cast<const float4*>(labels + (size_t)gwarp * FIN);
        unsigned long long h1 = 0ull, h2 = 0ull;
#pragma unroll
        for (int i = 0; i < 4; i++) {
            float4 v = row[lane + 32 * i];
            int fb = (lane + 32 * i) * 4;
            float vv[4] = {v.x, v.y, v.z, v.w};
#pragma unroll
            for (int j = 0; j < 4; j++) {
                unsigned int bits = __float_as_uint(vv[j]);
                if (vv[j] == 0.0f) bits = 0u;     // canonicalize -0 == +0
                unsigned long long x = (unsigned long long)bits
                    ^ ((unsigned long long)(fb + j + 1) * 0x9E3779B97F4A7C15ULL);
                h1 += mix64(x);
                h2 += mix64(x ^ 0xA5A5A5A5DEADBEEFULL);
            }
        }
#pragma unroll
        for (int o = 16; o > 0; o >>= 1) {
            h1 += __shfl_down_sync(0xffffffffu, h1, o);
            h2 += __shfl_down_sync(0xffffffffu, h2, o);
        }
        if (lane == 0) { g_h1[gwarp] = h1; g_h2[gwarp] = h2; }
    }

    // ======== phase 1: GEMM1  g_H = A @ W^T + bias ===========================
    // tile: n0 = (cta&7)*64, m0 = (cta>>3)*64. 8 warps: 4x2, warp tile 16x32.
    {
        float* As = dyn;            // [2][64][36]
        float* Bs = dyn + 4608;     // [2][64][36]
        const int n0 = (cta & 7) * 64;
        const int m0 = (cta >> 3) * 64;
        const int wr = wid >> 1;
        const int wc = wid & 1;
        const int r0 = tid >> 3;    // 0..31
        const int kc = tid & 7;

        const float* Arow = A + (size_t)(m0 + r0) * FIN + kc * 4;
        const float* Brow = W + (size_t)(n0 + r0) * FIN + kc * 4;

        float4 pa[2], pb[2];
        auto LDG = [&](int s) {
#pragma unroll
            for (int q = 0; q < 2; q++) {
                pa[q] = *reinterpret_cast<const float4*>(Arow + (size_t)(32 * q) * FIN + s * 32);
                pb[q] = *reinterpret_cast<const float4*>(Brow + (size_t)(32 * q) * FIN + s * 32);
            }
        };
        auto STS = [&](int buf) {
#pragma unroll
            for (int q = 0; q < 2; q++) {
                int r = r0 + 32 * q;
                float4 ca = make_float4(wmma::__float_to_tf32(pa[q].x), wmma::__float_to_tf32(pa[q].y),
                                        wmma::__float_to_tf32(pa[q].z), wmma::__float_to_tf32(pa[q].w));
                float4 cb = make_float4(wmma::__float_to_tf32(pb[q].x), wmma::__float_to_tf32(pb[q].y),
                                        wmma::__float_to_tf32(pb[q].z), wmma::__float_to_tf32(pb[q].w));
                *reinterpret_cast<float4*>(As + (size_t)buf * 2304 + r * 36 + kc * 4) = ca;
                *reinterpret_cast<float4*>(Bs + (size_t)buf * 2304 + r * 36 + kc * 4) = cb;
            }
        };

        wmma::fragment<wmma::accumulator, 16, 16, 8, float> c0, c1;
        wmma::fill_fragment(c0, 0.0f);
        wmma::fill_fragment(c1, 0.0f);

        LDG(0);
        STS(0);
        __syncthreads();

#pragma unroll 1
        for (int s = 0; s < 16; s++) {
            const int buf = s & 1;
            if (s + 1 < 16) LDG(s + 1);
#pragma unroll
            for (int ks = 0; ks < 4; ks++) {
                wmma::fragment<wmma::matrix_a, 16, 16, 8, wmma::precision::tf32, wmma::row_major> a;
                wmma::fragment<wmma::matrix_b, 16, 16, 8, wmma::precision::tf32, wmma::col_major> b0, b1;
                wmma::load_matrix_sync(a,  As + (size_t)buf * 2304 + (wr * 16) * 36 + ks * 8, 36);
                wmma::load_matrix_sync(b0, Bs + (size_t)buf * 2304 + (wc * 32) * 36 + ks * 8, 36);
                wmma::load_matrix_sync(b1, Bs + (size_t)buf * 2304 + (wc * 32 + 16) * 36 + ks * 8, 36);
                wmma::mma_sync(c0, a, b0, c0);
                wmma::mma_sync(c1, a, b1, c1);
            }
            if (s + 1 < 16) STS(buf ^ 1);
            __syncthreads();
        }

        // epilogue: stage [64][68] + bias + vectorized store
        float* stage = dyn;
        wmma::store_matrix_sync(stage + (size_t)(wr * 16) * 68 + wc * 32,      c0, 68, wmma::mem_row_major);
        wmma::store_matrix_sync(stage + (size_t)(wr * 16) * 68 + wc * 32 + 16, c1, 68, wmma::mem_row_major);
        __syncthreads();
#pragma unroll
        for (int t = 0; t < 4; t++) {
            int f4 = tid + t * 256;
            int row = f4 >> 4, c4 = (f4 & 15) * 4;
            float4 v = *reinterpret_cast<const float4*>(stage + (size_t)row * 68 + c4);
            float4 bv = *reinterpret_cast<const float4*>(bias + n0 + c4);
            v.x += bv.x; v.y += bv.y; v.z += bv.z; v.w += bv.w;
            *reinterpret_cast<float4*>(g_H + (size_t)(m0 + row) * FOUT + n0 + c4) = v;
        }
    }

    grid_barrier();                 // g_H complete

    // ======== phase 2: row norms (1024 warps, one row each) ==================
    {
        int gwarp = cta * 8 + wid;
        const float4* row = reinterpret_cast<const float4*>(g_H + (size_t)gwarp * FOUT);
        float ss = 0.0f;
#pragma unroll
        for (int i = 0; i < 4; i++) {
            float4 v = row[lane + 32 * i];
            ss += v.x * v.x + v.y * v.y + v.z * v.z + v.w * v.w;
        }
#pragma unroll
        for (int o = 16; o > 0; o >>= 1) ss += __shfl_xor_sync(0xffffffffu, ss, o);
        if (lane == 0) g_inv[gwarp] = 1.0f / fmaxf(sqrtf(ss), 1e-12f);
    }

    grid_barrier();                 // g_inv complete

    // ======== phase 3: fused Gram + softmax + KL (CTAs 0..63) ================
    if (cta < 64) {
        const int b = cta >> 4;           // 0..3
        const int m0 = (cta & 15) * 16;   // row tile
        const float* Hb = g_H + (size_t)b * PP * FOUT;
        float* Asm = dyn;                 // [2][16][36]
        float* Bsm = dyn + 1152;          // [2][256][36]

        {
            int q = tid;
            inv_s[q] = g_inv[b * PP + q];
            sh1[q] = g_h1[b * PP + q];
            sh2[q] = g_h2[b * PP + q];
        }

        float4 pb8[8], paq;
        auto LDG = [&](int c) {
#pragma unroll
            for (int it = 0; it < 8; it++) {
                int idx = tid + it * 256;           // 0..2047 = B tile f4 ids
                int row = idx >> 3, f = idx & 7;
                pb8[it] = *reinterpret_cast<const float4*>(Hb + (size_t)row * FOUT + c * 32 + f * 4);
            }
            if (tid < 128) {
                int row = tid >> 3, f = tid & 7;
                paq = *reinterpret_cast<const float4*>(Hb + (size_t)(m0 + row) * FOUT + c * 32 + f * 4);
            }
        };
        auto STS = [&](int buf) {
#pragma unroll
            for (int it = 0; it < 8; it++) {
                int idx = tid + it * 256;
                int row = idx >> 3, f = idx & 7;
                float4 v = pb8[it];
                float4 cv = make_float4(wmma::__float_to_tf32(v.x), wmma::__float_to_tf32(v.y),
                                        wmma::__float_to_tf32(v.z), wmma::__float_to_tf32(v.w));
                *reinterpret_cast<float4*>(Bsm + (size_t)buf * 9216 + row * 36 + f * 4) = cv;
            }
            if (tid < 128) {
                int row = tid >> 3, f = tid & 7;
                float4 v = paq;
                float4 cv = make_float4(wmma::__float_to_tf32(v.x), wmma::__float_to_tf32(v.y),
                                        wmma::__float_to_tf32(v.z), wmma::__float_to_tf32(v.w));
                *reinterpret_cast<float4*>(Asm + (size_t)buf * 576 + row * 36 + f * 4) = cv;
            }
        };

        wmma::fragment<wmma::accumulator, 16, 16, 8, float> c0, c1;
        wmma::fill_fragment(c0, 0.0f);
        wmma::fill_fragment(c1, 0.0f);

        LDG(0);
        STS(0);
        __syncthreads();

#pragma unroll 1
        for (int c = 0; c < 16; c++) {
            const int buf = c & 1;
            if (c + 1 < 16) LDG(c + 1);
#pragma unroll
            for (int ks = 0; ks < 4; ks++) {
                wmma::fragment<wmma::matrix_a, 16, 16, 8, wmma::precision::tf32, wmma::row_major> a;
                wmma::fragment<wmma::matrix_b, 16, 16, 8, wmma::precision::tf32, wmma::col_major> b0, b1;
                wmma::load_matrix_sync(a,  Asm + (size_t)buf * 576 + ks * 8, 36);
                wmma::load_matrix_sync(b0, Bsm + (size_t)buf * 9216 + (wid * 32) * 36 + ks * 8, 36);
                wmma::load_matrix_sync(b1, Bsm + (size_t)buf * 9216 + (wid * 32 + 16) * 36 + ks * 8, 36);
                wmma::mma_sync(c0, a, b0, c0);
                wmma::mma_sync(c1, a, b1, c1);
            }
            if (c + 1 < 16) STS(buf ^ 1);
            __syncthreads();
        }

        // stage S tile [16][260] over Bsm (all mma reads done)
        float* stageS = Bsm;
        wmma::store_matrix_sync(stageS + wid * 32,      c0, 260, wmma::mem_row_major);
        wmma::store_matrix_sync(stageS + wid * 32 + 16, c1, 260, wmma::mem_row_major);
        __syncthreads();

        const float INV_TAU = 1.0f / 0.07f;
        double local = 0.0;
#pragma unroll
        for (int rr = 0; rr < 2; rr++) {
            const int pl = wid * 2 + rr;
            const float* Sr = stageS + (size_t)pl * 260;
            const float ip = inv_s[m0 + pl] * INV_TAU;
            float s[8];
            float mx = -1e30f;
#pragma unroll
            for (int j = 0; j < 8; j++) {
                int q = lane + 32 * j;
                s[j] = Sr[q] * ip * inv_s[q];
                mx = fmaxf(mx, s[j]);
            }
#pragma unroll
            for (int o = 16; o > 0; o >>= 1) mx = fmaxf(mx, __shfl_xor_sync(0xffffffffu, mx, o));
            float z = 0.0f;
#pragma unroll
            for (int j = 0; j < 8; j++) z += __expf(s[j] - mx);
#pragma unroll
            for (int o = 16; o > 0; o >>= 1) z += __shfl_xor_sync(0xffffffffu, z, o);
            float lse = mx + logf(z);

            unsigned long long h1p = sh1[m0 + pl], h2p = sh2[m0 + pl];
            int cnt = 0;
            bool match[8];
#pragma unroll
            for (int j = 0; j < 8; j++) {
                int q = lane + 32 * j;
                match[j] = (sh1[q] == h1p) && (sh2[q] == h2p);
                cnt += match[j] ? 1 : 0;
            }
#pragma unroll
            for (int o = 16; o > 0; o >>= 1) cnt += __shfl_xor_sync(0xffffffffu, cnt, o);

            float logn = logf((float)cnt);
            float contrib = 0.0f;
#pragma unroll
            for (int j = 0; j < 8; j++) {
                if (match[j]) {
                    float lp = s[j] - lse;
                    lp = fminf(fmaxf(lp, -11.512925464970229f),      // log(1e-5)
                               -1.0000050000290891e-05f);            // log(1-1e-5)
                    contrib += (-logn - lp);
                }
            }
#pragma unroll
            for (int o = 16; o > 0; o >>= 1) contrib += __shfl_xor_sync(0xffffffffu, contrib, o);
            if (lane == 0) local += (double)contrib / (double)cnt;
        }
        if (lane == 0) wsum[wid] = local;
        __syncthreads();
        if (tid == 0) {
            double blk = 0.0;
#pragma unroll
            for (int i = 0; i < 8; i++) blk += wsum[i];
            atomicAdd(&g_loss, blk);
            __threadfence();
            // last phase-3 finisher writes the output (no extra kernel)
            if (atomicAdd(&g_done, 1u) == 63u) {
                *(volatile unsigned int*)&g_done = 0;
                double l = atomicAdd(&g_loss, 0.0);   // coherent read of final sum
                out[0] = (float)(l * (1.0 / (double)(BB * PP)));
            }
        }
    }
}

// ================= launch ====================================================
extern "C" void kernel_launch(void* const* d_in, const int* in_sizes, int n_in,
                              void* d_out, int out_size) {
    const float* inputs = (const float*)d_in[0];
    const float* labels = (const float*)d_in[1];
    const float* W      = (const float*)d_in[2];
    const float* bias   = (const float*)d_in[3];
    float* out = (float*)d_out;

    const int DYN_SMEM = 19584 * 4;    // 78336 B (phase-3 footprint)
    cudaFuncSetAttribute(fused_all, cudaFuncAttributeMaxDynamicSharedMemorySize, DYN_SMEM);
    fused_all<<<NCTA, 256, DYN_SMEM>>>(inputs, labels, W, bias, out);
}

// round 7
// speedup vs baseline: 1.2522x; 1.2434x over previous
#include <cuda_runtime.h>
#include <mma.h>
#include <cstdint>
#include <cstddef>

using namespace nvcuda;

#define BB 4
#define PP 256
#define FIN 512
#define FOUT 512
#define NROWS (BB*PP)   // 1024

// ---------------- device scratch (no allocations allowed) -------------------
__device__ float g_H[NROWS * FOUT];          // fc output, tf32-rounded fp32 (2 MB)
__device__ float g_ss2[8][NROWS];            // per-nblock partial sum-of-squares
__device__ unsigned long long g_h1[NROWS];
__device__ unsigned long long g_h2[NROWS];
__device__ double g_loss;
__device__ unsigned int g_done = 0;          // K2 completion count (self-reset)

// ---------------- cp.async helpers ------------------------------------------
__device__ __forceinline__ void cp16(uint32_t saddr, const void* gptr) {
    asm volatile("cp.async.cg.shared.global [%0], [%1], 16;" :: "r"(saddr), "l"(gptr));
}
#define CP_COMMIT() asm volatile("cp.async.commit_group;" ::: "memory")
#define CP_WAIT(n)  asm volatile("cp.async.wait_group %0;" :: "n"(n) : "memory")

__device__ __forceinline__ unsigned long long mix64(unsigned long long x) {
    x ^= x >> 30; x *= 0xbf58476d1ce4e5b9ULL;
    x ^= x >> 27; x *= 0x94d049bb133111ebULL;
    x ^= x >> 31;
    return x;
}

// ================= K1: hash + GEMM1 + norm partials ==========================
// g_H = round_tf32(inputs @ W^T + bias). 128 CTAs x 256 thr, 64x64 tiles.
// 8 warps: 4x2 grid, warp tile 16x32. cp.async double-buffered, BK=32.
__global__ __launch_bounds__(256, 1)
void k1_gemm(const float* __restrict__ A, const float* __restrict__ labels,
             const float* __restrict__ W, const float* __restrict__ bias) {
    extern __shared__ float dyn[];            // [2][2][64][36] : A,B double-buffered
    const int cta = blockIdx.x;
    const int tid = threadIdx.x;
    const int wid = tid >> 5, lane = tid & 31;

    if (cta == 0 && tid == 0) g_loss = 0.0;

    // ---- hash: 128 CTAs x 8 warps = 1024 label rows
    {
        int gwarp = cta * 8 + wid;
        const float4* row = reinterpret_cast<const float4*>(labels + (size_t)gwarp * FIN);
        unsigned long long h1 = 0ull, h2 = 0ull;
#pragma unroll
        for (int i = 0; i < 4; i++) {
            float4 v = row[lane + 32 * i];
            int fb = (lane + 32 * i) * 4;
            float vv[4] = {v.x, v.y, v.z, v.w};
#pragma unroll
            for (int j = 0; j < 4; j++) {
                unsigned int bits = __float_as_uint(vv[j]);
                if (vv[j] == 0.0f) bits = 0u;
                unsigned long long x = (unsigned long long)bits
                    ^ ((unsigned long long)(fb + j + 1) * 0x9E3779B97F4A7C15ULL);
                h1 += mix64(x);
                h2 += mix64(x ^ 0xA5A5A5A5DEADBEEFULL);
            }
        }
#pragma unroll
        for (int o = 16; o > 0; o >>= 1) {
            h1 += __shfl_down_sync(0xffffffffu, h1, o);
            h2 += __shfl_down_sync(0xffffffffu, h2, o);
        }
        if (lane == 0) { g_h1[gwarp] = h1; g_h2[gwarp] = h2; }
    }

    // ---- GEMM
    const int nb = cta & 7;
    const int n0 = nb * 64;
    const int m0 = (cta >> 3) * 64;
    float* As = dyn;                          // [2][64][36]
    float* Bs = dyn + 2 * 64 * 36;            // [2][64][36]
    uint32_t As_s = (uint32_t)__cvta_generic_to_shared(As);
    uint32_t Bs_s = (uint32_t)__cvta_generic_to_shared(Bs);

    const int wr = wid >> 1, wc = wid & 1;
    const int r0 = tid >> 3;                  // 0..31
    const int kc = tid & 7;

    auto PREFETCH = [&](int s, int buf) {
        // A: 512 f4 (rows 0..63 x 8 f4), B same. 1024 f4 / 256 thr = 4 each.
#pragma unroll
        for (int q = 0; q < 2; q++) {
            int r = r0 + 32 * q;
            cp16(As_s + ((size_t)buf * 2304 + r * 36 + kc * 4) * 4,
                 A + (size_t)(m0 + r) * FIN + s * 32 + kc * 4);
            cp16(Bs_s + ((size_t)buf * 2304 + r * 36 + kc * 4) * 4,
                 W + (size_t)(n0 + r) * FIN + s * 32 + kc * 4);
        }
        CP_COMMIT();
    };

    wmma::fragment<wmma::accumulator, 16, 16, 8, float> c0, c1;
    wmma::fill_fragment(c0, 0.0f);
    wmma::fill_fragment(c1, 0.0f);

    PREFETCH(0, 0);
#pragma unroll 1
    for (int s = 0; s < 16; s++) {
        const int buf = s & 1;
        if (s + 1 < 16) PREFETCH(s + 1, buf ^ 1);
        if (s + 1 < 16) { CP_WAIT(1); } else { CP_WAIT(0); }
        __syncthreads();
#pragma unroll
        for (int ks = 0; ks < 4; ks++) {
            wmma::fragment<wmma::matrix_a, 16, 16, 8, wmma::precision::tf32, wmma::row_major> a;
            wmma::fragment<wmma::matrix_b, 16, 16, 8, wmma::precision::tf32, wmma::col_major> b0, b1;
            wmma::load_matrix_sync(a,  As + (size_t)buf * 2304 + (wr * 16) * 36 + ks * 8, 36);
            wmma::load_matrix_sync(b0, Bs + (size_t)buf * 2304 + (wc * 32) * 36 + ks * 8, 36);
            wmma::load_matrix_sync(b1, Bs + (size_t)buf * 2304 + (wc * 32 + 16) * 36 + ks * 8, 36);
            wmma::mma_sync(c0, a, b0, c0);
            wmma::mma_sync(c1, a, b1, c1);
        }
        __syncthreads();
    }

    // ---- epilogue: stage, +bias, round to tf32, store, per-row SS partials
    float* stage = dyn;                       // [64][68]
    wmma::store_matrix_sync(stage + (size_t)(wr * 16) * 68 + wc * 32,      c0, 68, wmma::mem_row_major);
    wmma::store_matrix_sync(stage + (size_t)(wr * 16) * 68 + wc * 32 + 16, c1, 68, wmma::mem_row_major);
    __syncthreads();
#pragma unroll
    for (int t = 0; t < 4; t++) {
        int f4 = tid + t * 256;
        int row = f4 >> 4, c4 = (f4 & 15) * 4;
        float4 v = *reinterpret_cast<const float4*>(stage + (size_t)row * 68 + c4);
        float4 bv = *reinterpret_cast<const float4*>(bias + n0 + c4);
        v.x = wmma::__float_to_tf32(v.x + bv.x);
        v.y = wmma::__float_to_tf32(v.y + bv.y);
        v.z = wmma::__float_to_tf32(v.z + bv.z);
        v.w = wmma::__float_to_tf32(v.w + bv.w);
        *reinterpret_cast<float4*>(stage + (size_t)row * 68 + c4) = v;
        *reinterpret_cast<float4*>(g_H + (size_t)(m0 + row) * FOUT + n0 + c4) = v;
    }
    __syncthreads();
    {
        int row = tid >> 2;                   // 64 rows x 4 threads
        int cg = (tid & 3) * 16;
        float ss = 0.0f;
#pragma unroll
        for (int i = 0; i < 4; i++) {
            float4 v = *reinterpret_cast<const float4*>(stage + (size_t)row * 68 + cg + i * 4);
            ss += v.x * v.x + v.y * v.y + v.z * v.z + v.w * v.w;
        }
        ss += __shfl_xor_sync(0xffffffffu, ss, 1);
        ss += __shfl_xor_sync(0xffffffffu, ss, 2);
        if ((tid & 3) == 0) g_ss2[nb][m0 + row] = ss;
    }
}

// ================= K2: fused Gram + softmax + KL =============================
// 64 CTAs x 256 thr (8 warps): CTA = (batch b, 16-row tile). cp.async stream.
__global__ __launch_bounds__(256, 1)
void k2_gram_kl(float* __restrict__ out) {
    extern __shared__ float dyn[];
    float* Asm = dyn;                         // [2][16][36]
    float* Bsm = dyn + 2 * 16 * 36;           // [2][256][36]
    uint32_t Asm_s = (uint32_t)__cvta_generic_to_shared(Asm);
    uint32_t Bsm_s = (uint32_t)__cvta_generic_to_shared(Bsm);
    __shared__ float inv_s[PP];
    __shared__ unsigned long long sh1[PP];
    __shared__ unsigned long long sh2[PP];
    __shared__ double wsum[8];

    const int cta = blockIdx.x;
    const int b = cta >> 4;
    const int m0 = (cta & 15) * 16;
    const int tid = threadIdx.x;
    const int wid = tid >> 5, lane = tid & 31;
    const float* Hb = g_H + (size_t)b * PP * FOUT;

    auto PREFETCH = [&](int c, int buf) {
#pragma unroll
        for (int it = 0; it < 8; it++) {      // B: 2048 f4
            int idx = tid + it * 256;
            int row = idx >> 3, f = idx & 7;
            cp16(Bsm_s + ((size_t)buf * 9216 + row * 36 + f * 4) * 4,
                 Hb + (size_t)row * FOUT + c * 32 + f * 4);
        }
        if (tid < 128) {                      // A: 128 f4
            int row = tid >> 3, f = tid & 7;
            cp16(Asm_s + ((size_t)buf * 576 + row * 36 + f * 4) * 4,
                 Hb + (size_t)(m0 + row) * FOUT + c * 32 + f * 4);
        }
        CP_COMMIT();
    };

    PREFETCH(0, 0);

    // metadata loads overlap with first prefetch
    {
        int q = tid;
        float ss = 0.0f;
#pragma unroll
        for (int nb = 0; nb < 8; nb++) ss += g_ss2[nb][b * PP + q];
        inv_s[q] = 1.0f / fmaxf(sqrtf(ss), 1e-12f);
        sh1[q] = g_h1[b * PP + q];
        sh2[q] = g_h2[b * PP + q];
    }

    wmma::fragment<wmma::accumulator, 16, 16, 8, float> c0, c1;
    wmma::fill_fragment(c0, 0.0f);
    wmma::fill_fragment(c1, 0.0f);

#pragma unroll 1
    for (int c = 0; c < 16; c++) {
        const int buf = c & 1;
        if (c + 1 < 16) PREFETCH(c + 1, buf ^ 1);
        if (c + 1 < 16) { CP_WAIT(1); } else { CP_WAIT(0); }
        __syncthreads();
#pragma unroll
        for (int ks = 0; ks < 4; ks++) {
            wmma::fragment<wmma::matrix_a, 16, 16, 8, wmma::precision::tf32, wmma::row_major> a;
            wmma::fragment<wmma::matrix_b, 16, 16, 8, wmma::precision::tf32, wmma::col_major> b0, b1;
            wmma::load_matrix_sync(a,  Asm + (size_t)buf * 576 + ks * 8, 36);
            wmma::load_matrix_sync(b0, Bsm + (size_t)buf * 9216 + (wid * 32) * 36 + ks * 8, 36);
            wmma::load_matrix_sync(b1, Bsm + (size_t)buf * 9216 + (wid * 32 + 16) * 36 + ks * 8, 36);
            wmma::mma_sync(c0, a, b0, c0);
            wmma::mma_sync(c1, a, b1, c1);
        }
        __syncthreads();
    }

    // ---- stage S tile [16][260] over Bsm (mma reads done)
    float* stageS = Bsm;
    wmma::store_matrix_sync(stageS + wid * 32,      c0, 260, wmma::mem_row_major);
    wmma::store_matrix_sync(stageS + wid * 32 + 16, c1, 260, wmma::mem_row_major);
    __syncthreads();

    // ---- softmax + KL: 8 warps x 2 rows
    const float INV_TAU = 1.0f / 0.07f;
    double local = 0.0;
#pragma unroll
    for (int rr = 0; rr < 2; rr++) {
        const int pl = wid * 2 + rr;
        const float* Sr = stageS + (size_t)pl * 260;
        const float ip = inv_s[m0 + pl] * INV_TAU;
        float s[8];
        float mx = -1e30f;
#pragma unroll
        for (int j = 0; j < 8; j++) {
            int q = lane + 32 * j;
            s[j] = Sr[q] * ip * inv_s[q];
            mx = fmaxf(mx, s[j]);
        }
#pragma unroll
        for (int o = 16; o > 0; o >>= 1) mx = fmaxf(mx, __shfl_xor_sync(0xffffffffu, mx, o));
        float z = 0.0f;
#pragma unroll
        for (int j = 0; j < 8; j++) z += __expf(s[j] - mx);
#pragma unroll
        for (int o = 16; o > 0; o >>= 1) z += __shfl_xor_sync(0xffffffffu, z, o);
        float lse = mx + logf(z);

        unsigned long long h1p = sh1[m0 + pl], h2p = sh2[m0 + pl];
        int cnt = 0;
        bool match[8];
#pragma unroll
        for (int j = 0; j < 8; j++) {
            int q = lane + 32 * j;
            match[j] = (sh1[q] == h1p) && (sh2[q] == h2p);
            cnt += match[j] ? 1 : 0;
        }
#pragma unroll
        for (int o = 16; o > 0; o >>= 1) cnt += __shfl_xor_sync(0xffffffffu, cnt, o);

        float logn = logf((float)cnt);
        float contrib = 0.0f;
#pragma unroll
        for (int j = 0; j < 8; j++) {
            if (match[j]) {
                float lp = s[j] - lse;
                lp = fminf(fmaxf(lp, -11.512925464970229f),      // log(1e-5)
                           -1.0000050000290891e-05f);            // log(1-1e-5)
                contrib += (-logn - lp);
            }
        }
#pragma unroll
        for (int o = 16; o > 0; o >>= 1) contrib += __shfl_xor_sync(0xffffffffu, contrib, o);
        if (lane == 0) local += (double)contrib / (double)cnt;
    }
    if (lane == 0) wsum[wid] = local;
    __syncthreads();
    if (tid == 0) {
        double blk = 0.0;
#pragma unroll
        for (int i = 0; i < 8; i++) blk += wsum[i];
        atomicAdd(&g_loss, blk);
        __threadfence();
        if (atomicAdd(&g_done, 1u) == 63u) {     // last finisher writes output
            *(volatile unsigned int*)&g_done = 0;
            double l = atomicAdd(&g_loss, 0.0);
            out[0] = (float)(l * (1.0 / (double)(BB * PP)));
        }
    }
}

// ================= launch ====================================================
extern "C" void kernel_launch(void* const* d_in, const int* in_sizes, int n_in,
                              void* d_out, int out_size) {
    const float* inputs = (const float*)d_in[0];
    const float* labels = (const float*)d_in[1];
    const float* W      = (const float*)d_in[2];
    const float* bias   = (const float*)d_in[3];
    float* out = (float*)d_out;

    const int K1_SMEM = 2 * 2 * 64 * 36 * 4;          // 36864 B
    const int K2_SMEM = (2 * 16 * 36 + 2 * 256 * 36) * 4;   // 78336 B
    cudaFuncSetAttribute(k1_gemm,    cudaFuncAttributeMaxDynamicSharedMemorySize, K1_SMEM);
    cudaFuncSetAttribute(k2_gram_kl, cudaFuncAttributeMaxDynamicSharedMemorySize, K2_SMEM);

    k1_gemm<<<128, 256, K1_SMEM>>>(inputs, labels, W, bias);
    k2_gram_kl<<<64, 256, K2_SMEM>>>(out);
}